// round 6
// baseline (speedup 1.0000x reference)
#include <cuda_runtime.h>

// out[b,e] = sparsity[b,e] * sum_{m,h} hidden[b,m,h] * ws[e,h]
//   ws[e,h] = sum_n weight[e,h,n]   (32 MB read)  -> kernel 1 (pure streaming)
//   dot is linear in m -> kernel 2: one block per (b,m) row, direct RED into out.
// A=1, B=32, M=32, H=1024, E=8, N=1024.

#define Bn 32
#define Mn 32
#define Hn 1024
#define En 8
#define Nn 1024

__device__ float g_wsT[Hn * En];   // wsT[h*8 + e]  (32 KB, L1/L2-resident)

// ---- Kernel 1: pure weight row-sum streaming (unchanged from R5, ~5.5us).
// 512 blocks x 256 threads; warp w owns rows r0=bid*16+2w, r0+1. Block 0 zeroes out.
__global__ void __launch_bounds__(256) weight_kernel(
    const float* __restrict__ weight,
    float* __restrict__ out)
{
    const int tid  = threadIdx.x;
    const int lane = tid & 31;
    const int wid  = tid >> 5;
    const int r0   = blockIdx.x * 16 + wid * 2;

    const float4* rowA = reinterpret_cast<const float4*>(weight + (size_t)r0 * Nn);
    const float4* rowB = reinterpret_cast<const float4*>(weight + (size_t)(r0 + 1) * Nn);

    float s0 = 0.f, s1 = 0.f;
    #pragma unroll
    for (int k = 0; k < Nn / 4 / 32; k++) {
        float4 a = rowA[lane + k * 32];
        float4 b = rowB[lane + k * 32];
        s0 += (a.x + a.y) + (a.z + a.w);
        s1 += (b.x + b.y) + (b.z + b.w);
    }
    #pragma unroll
    for (int off = 16; off > 0; off >>= 1) {
        s0 += __shfl_xor_sync(0xffffffffu, s0, off);
        s1 += __shfl_xor_sync(0xffffffffu, s1, off);
    }
    if (lane == 0) {
        const int e  = r0 >> 10;
        const int h0 = r0 & (Hn - 1);
        g_wsT[h0 * En + e]       = s0;
        g_wsT[(h0 + 1) * En + e] = s1;
    }
    if (blockIdx.x == 0) out[tid] = 0.f;   // zero all 256 outputs
}

// ---- Kernel 2: 1024 blocks x 128 threads, one block per (b,m).
// Block reads hidden[b,m,:] (4 KB contiguous, 2 float4/thread), multiplies by
// wsT (cached), reduces p[8] across the block, 8 REDs into out.
__global__ void __launch_bounds__(128) hidden_dot_kernel(
    const float* __restrict__ hidden,
    const float* __restrict__ sparsity,
    float* __restrict__ out)
{
    const int bid  = blockIdx.x;
    const int tid  = threadIdx.x;
    const int lane = tid & 31;
    const int wid  = tid >> 5;
    const int b    = bid >> 5;          // [0,32)
    const int m    = bid & 31;          // [0,32)

    const float4* row = reinterpret_cast<const float4*>(
        hidden + ((size_t)b * Mn + m) * Hn);

    float p[8] = {0.f, 0.f, 0.f, 0.f, 0.f, 0.f, 0.f, 0.f};

    #pragma unroll
    for (int k = 0; k < 2; k++) {               // 2 float4 per thread
        const int h4 = tid + k * 128;           // float4 index in [0,256)
        float4 v = row[h4];
        const float4* wt = reinterpret_cast<const float4*>(g_wsT + h4 * 4 * En);
        // 4 h values, each with 8 contiguous ws floats
        float vv[4] = {v.x, v.y, v.z, v.w};
        #pragma unroll
        for (int j = 0; j < 4; j++) {
            float4 w0 = wt[j * 2];
            float4 w1 = wt[j * 2 + 1];
            p[0] += vv[j] * w0.x;  p[1] += vv[j] * w0.y;
            p[2] += vv[j] * w0.z;  p[3] += vv[j] * w0.w;
            p[4] += vv[j] * w1.x;  p[5] += vv[j] * w1.y;
            p[6] += vv[j] * w1.z;  p[7] += vv[j] * w1.w;
        }
    }

    #pragma unroll
    for (int off = 16; off > 0; off >>= 1)
        #pragma unroll
        for (int e = 0; e < 8; e++)
            p[e] += __shfl_xor_sync(0xffffffffu, p[e], off);

    __shared__ float sm[4][8];
    if (lane == 0)
        #pragma unroll
        for (int e = 0; e < 8; e++) sm[wid][e] = p[e];
    __syncthreads();

    if (tid < En) {
        const float v = sm[0][tid] + sm[1][tid] + sm[2][tid] + sm[3][tid];
        const int idx = b * En + tid;
        atomicAdd(&out[idx], v * sparsity[idx]);
    }
}

extern "C" void kernel_launch(void* const* d_in, const int* in_sizes, int n_in,
                              void* d_out, int out_size)
{
    const float* hidden   = (const float*)d_in[0];
    const float* sparsity = (const float*)d_in[1];
    const float* weight   = (const float*)d_in[2];
    float* out = (float*)d_out;

    weight_kernel<<<(En * Hn) / 16, 256>>>(weight, out);            // 512 blocks
    hidden_dot_kernel<<<Bn * Mn, 128>>>(hidden, sparsity, out);     // 1024 blocks
}

// round 7
// speedup vs baseline: 1.5685x; 1.5685x over previous
#include <cuda_runtime.h>

// out[b,e] = sparsity[b,e] * sum_h hs[b,h] * ws[e,h]
//   ws[e,h] = sum_n weight[e,h,n]   (32 MB)  -> kernel 1, pure streaming (proven)
//   hs + dot                        (4 MB)   -> kernel 2, contiguous reads + tiny RED
// A=1, B=32, M=32, H=1024, E=8, N=1024.

#define Bn 32
#define Mn 32
#define Hn 1024
#define En 8
#define Nn 1024

__device__ float g_wsT[Hn * En];   // wsT[h*8 + e]  (32 KB, L2-resident)

// ---- Kernel 1: pure weight row-sum streaming (R5 verbatim, ~5.5us).
__global__ void __launch_bounds__(256) weight_kernel(
    const float* __restrict__ weight,
    float* __restrict__ out)
{
    const int tid  = threadIdx.x;
    const int lane = tid & 31;
    const int wid  = tid >> 5;
    const int r0   = blockIdx.x * 16 + wid * 2;

    const float4* rowA = reinterpret_cast<const float4*>(weight + (size_t)r0 * Nn);
    const float4* rowB = reinterpret_cast<const float4*>(weight + (size_t)(r0 + 1) * Nn);

    float s0 = 0.f, s1 = 0.f;
    #pragma unroll
    for (int k = 0; k < Nn / 4 / 32; k++) {
        float4 a = rowA[lane + k * 32];
        float4 b = rowB[lane + k * 32];
        s0 += (a.x + a.y) + (a.z + a.w);
        s1 += (b.x + b.y) + (b.z + b.w);
    }
    #pragma unroll
    for (int off = 16; off > 0; off >>= 1) {
        s0 += __shfl_xor_sync(0xffffffffu, s0, off);
        s1 += __shfl_xor_sync(0xffffffffu, s1, off);
    }
    if (lane == 0) {
        const int e  = r0 >> 10;
        const int h0 = r0 & (Hn - 1);
        g_wsT[h0 * En + e]       = s0;
        g_wsT[(h0 + 1) * En + e] = s1;
    }
    if (blockIdx.x == 0) out[tid] = 0.f;   // zero all 256 outputs
}

// ---- Kernel 2: hidden reduce + dot. 512 blocks x 128 threads.
// Block (b, hc): b = bid>>4, hc = bid&15 covers h in [hc*64, hc*64+64).
// Thread (g, c): g = tid>>4 (m-group of 4), c = tid&15 (float4 column).
// Loads are CONTIGUOUS along h (16 threads x float4 = 256B per row segment);
// 4 independent LDG.128 per thread. Reduce over m via 2KB smem tile; 16 lanes
// do the 64-h dot vs wsT (32 LDG.128 of wsT per block); 8 REDs per block.
__global__ void __launch_bounds__(128) hidden_dot_kernel(
    const float* __restrict__ hidden,
    const float* __restrict__ sparsity,
    float* __restrict__ out)
{
    const int bid = blockIdx.x;
    const int tid = threadIdx.x;
    const int b   = bid >> 4;          // [0,32)
    const int hc  = bid & 15;          // [0,16) chunk of 64 h
    const int g   = tid >> 4;          // [0,8)  m-group
    const int c   = tid & 15;          // [0,16) float4 column

    const float4* H4 = reinterpret_cast<const float4*>(hidden);
    const size_t baseB = (size_t)b * Mn * (Hn / 4) + hc * 16 + c;

    float4 acc = make_float4(0.f, 0.f, 0.f, 0.f);
    #pragma unroll
    for (int mm = 0; mm < 4; mm++) {               // 4 independent LDG.128
        const int m = g * 4 + mm;
        float4 v = H4[baseB + (size_t)m * (Hn / 4)];
        acc.x += v.x; acc.y += v.y; acc.z += v.z; acc.w += v.w;
    }

    __shared__ float4 sm[8][16];
    sm[g][c] = acc;
    __syncthreads();

    if (tid < 16) {
        float4 hsv = sm[0][tid];
        #pragma unroll
        for (int j = 1; j < 8; j++) {
            float4 v = sm[j][tid];
            hsv.x += v.x; hsv.y += v.y; hsv.z += v.z; hsv.w += v.w;
        }
        const int h0 = hc * 64 + tid * 4;          // first h of this thread's quad
        const float4* wt = reinterpret_cast<const float4*>(g_wsT + h0 * En);

        float p[8] = {0.f, 0.f, 0.f, 0.f, 0.f, 0.f, 0.f, 0.f};
        float vv[4] = {hsv.x, hsv.y, hsv.z, hsv.w};
        #pragma unroll
        for (int j = 0; j < 4; j++) {              // 8 LDG.128 of wsT per thread
            float4 w0 = wt[j * 2];
            float4 w1 = wt[j * 2 + 1];
            p[0] += vv[j] * w0.x;  p[1] += vv[j] * w0.y;
            p[2] += vv[j] * w0.z;  p[3] += vv[j] * w0.w;
            p[4] += vv[j] * w1.x;  p[5] += vv[j] * w1.y;
            p[6] += vv[j] * w1.z;  p[7] += vv[j] * w1.w;
        }
        // reduce across the 16 active lanes (all in warp 0, converged)
        #pragma unroll
        for (int off = 8; off > 0; off >>= 1)
            #pragma unroll
            for (int e = 0; e < 8; e++)
                p[e] += __shfl_xor_sync(0x0000FFFFu, p[e], off);

        if (tid == 0) {
            const float4* sp = reinterpret_cast<const float4*>(sparsity + b * En);
            float4 sA = sp[0], sB = sp[1];
            float sv[8] = {sA.x, sA.y, sA.z, sA.w, sB.x, sB.y, sB.z, sB.w};
            #pragma unroll
            for (int e = 0; e < 8; e++)
                atomicAdd(&out[b * En + e], p[e] * sv[e]);   // 8 REDs/block
        }
    }
}

extern "C" void kernel_launch(void* const* d_in, const int* in_sizes, int n_in,
                              void* d_out, int out_size)
{
    const float* hidden   = (const float*)d_in[0];
    const float* sparsity = (const float*)d_in[1];
    const float* weight   = (const float*)d_in[2];
    float* out = (float*)d_out;

    weight_kernel<<<(En * Hn) / 16, 256>>>(weight, out);          // 512 blocks
    hidden_dot_kernel<<<Bn * 16, 128>>>(hidden, sparsity, out);   // 512 blocks
}